// round 14
// baseline (speedup 1.0000x reference)
#include <cuda_runtime.h>
#include <cuda_fp16.h>
#include <cstdint>

#define NN   50000
#define KK   25
#define FF   128
#define TT   256
#define OUTD 128
#define NBLK 148
#define NKTOT 1250000
#define EPSB 1e-3f
#define NTILES (NN / 5)          /* 10000 */
#define ROWS_T 125               /* 5 nodes * 25 */
#define C1NB 148
#define C2NB 148
#define NSTG4 4000
#define NTL2 391                 /* ceil(50000/128) */

typedef unsigned long long u64;
typedef unsigned int u32;

// ---------------- smem layout for passB ----------------
#define SM_AHI  0
#define SM_B    69632
#define SM_STG  137216
#define SM_TOTAL (137216 + 64000)   /* 201216 */
#define ASTR 272
#define BSTR 528
#define ZHSTR 264

// ---------------- smem layout for passC2h ----------------
#define C2A   0                     /* A fp16: 128 rows x 528B = 67584; zbuf f32 128x132 aliases */
#define C2B   67584                 /* B fp16: 256 rows x 272B = 69632 */
#define C2AC  137216                /* a1/c1/mu/muTmp/muWn: 1152 floats */
#define SM2_TOTAL (137216 + 4608)   /* 141824 */
#define ZST2  132

// ---------------- scratch ----------------
__device__ float d_poolZ[(size_t)NN * TT];
__device__ float d_SW[(size_t)NN * OUTD];
__device__ float d_PW[(size_t)NN * OUTD];
__device__ float d_pBs2[NBLK * 256];
__device__ float d_pBq2[NBLK * 256];
__device__ float d_pC1s[C1NB * 256];
__device__ float d_pC1q[C1NB * 256];
__device__ float d_pC2s[C2NB * 256];
__device__ float d_pC2q[C2NB * 256];
__device__ float d_a1[TT], d_c1[TT];
__device__ float d_a2[256], d_c2[256];

// ---------------- helpers ----------------
__device__ __forceinline__ u32 smem_u32(const void* p) {
    u32 a;
    asm("{ .reg .u64 t; cvta.to.shared.u64 t, %1; cvt.u32.u64 %0, t; }" : "=r"(a) : "l"(p));
    return a;
}
__device__ __forceinline__ void ldsm4(u32 a, u32& r0, u32& r1, u32& r2, u32& r3) {
    asm volatile("ldmatrix.sync.aligned.m8n8.x4.shared.b16 {%0,%1,%2,%3}, [%4];"
                 : "=r"(r0), "=r"(r1), "=r"(r2), "=r"(r3) : "r"(a));
}
__device__ __forceinline__ void ldsm4t(u32 a, u32& r0, u32& r1, u32& r2, u32& r3) {
    asm volatile("ldmatrix.sync.aligned.m8n8.x4.trans.shared.b16 {%0,%1,%2,%3}, [%4];"
                 : "=r"(r0), "=r"(r1), "=r"(r2), "=r"(r3) : "r"(a));
}
__device__ __forceinline__ void mma16816h(float* d, const u32* a, u32 b0, u32 b1) {
    asm volatile(
        "mma.sync.aligned.m16n8k16.row.col.f32.f16.f16.f32 "
        "{%0,%1,%2,%3}, {%4,%5,%6,%7}, {%8,%9}, {%0,%1,%2,%3};"
        : "+f"(d[0]), "+f"(d[1]), "+f"(d[2]), "+f"(d[3])
        : "r"(a[0]), "r"(a[1]), "r"(a[2]), "r"(a[3]), "r"(b0), "r"(b1));
}
__device__ __forceinline__ u64 pack2(float lo, float hi) {
    u64 r;
    asm("mov.b64 %0, {%1, %2};" : "=l"(r) : "f"(lo), "f"(hi));
    return r;
}
__device__ __forceinline__ void fma2(u64& acc, u64 a, u64 b) {
    asm("fma.rn.f32x2 %0, %1, %2, %0;" : "+l"(acc) : "l"(a), "l"(b));
}
__device__ __forceinline__ float2 unpack2(u64 v) {
    float lo, hi;
    asm("mov.b64 {%0, %1}, %2;" : "=f"(lo), "=f"(hi) : "l"(v));
    return make_float2(lo, hi);
}
__device__ __forceinline__ void cp_async16(u32 dst, const void* src) {
    asm volatile("cp.async.cg.shared.global [%0], [%1], 16;" :: "r"(dst), "l"(src));
}
#define CP_COMMIT() asm volatile("cp.async.commit_group;" ::: "memory")
#define CP_WAIT0()  asm volatile("cp.async.wait_group 0;" ::: "memory")

// ================= pass B: byte-identical to R12/R13 (register-cliff rule: untouched) =================
__global__ void __launch_bounds__(256, 1)
passB(const float* __restrict__ neigh, const float* __restrict__ Wt,
      const float* __restrict__ g1) {
    extern __shared__ char smem[];
    const u32 sb = smem_u32(smem);
    const int tid = threadIdx.x;
    const int lane = tid & 31;
    const int wid = tid >> 5;
    const int g8 = lane >> 2;
    const int tig = lane & 3;
    const int mwarp = wid & 3;
    const int nwarp = wid >> 2;
    const int m0 = mwarp * 32;
    const int n0 = nwarp * 128;
    const float4* stg4 = (const float4*)(smem + SM_STG);

    {
        const float4* src = (const float4*)(neigh + (size_t)blockIdx.x * (ROWS_T * FF));
#pragma unroll
        for (int u = 0; u < 16; ++u) {
            int idx = tid + u * 256;
            if (idx < NSTG4) cp_async16(sb + SM_STG + idx * 16, src + idx);
        }
        CP_COMMIT();
    }

    for (int idx = tid; idx < FF * 64; idx += 256) {
        int k = idx >> 6, n4 = idx & 63;
        float4 v = ((const float4*)Wt)[idx];
        uint2 uh;
        asm("cvt.rn.f16x2.f32 %0, %1, %2;" : "=r"(uh.x) : "f"(v.y), "f"(v.x));
        asm("cvt.rn.f16x2.f32 %0, %1, %2;" : "=r"(uh.y) : "f"(v.w), "f"(v.z));
        *(uint2*)(smem + SM_B + k * BSTR + n4 * 8) = uh;
    }

    const int a_row_l = lane & 15;
    const int a_koff  = (lane >> 4) << 3;
    float sAcc = 0.f, qAcc = 0.f;

    for (int gt = blockIdx.x; gt < NTILES; gt += NBLK) {
        CP_WAIT0();
        __syncthreads();

        for (int idx = tid; idx < NSTG4; idx += 256) {
            float4 v = stg4[idx];
            int r = idx >> 5, c4 = idx & 31;
            uint2 uh;
            asm("cvt.rn.f16x2.f32 %0, %1, %2;" : "=r"(uh.x) : "f"(v.y), "f"(v.x));
            asm("cvt.rn.f16x2.f32 %0, %1, %2;" : "=r"(uh.y) : "f"(v.w), "f"(v.z));
            *(uint2*)(smem + SM_AHI + r * ASTR + c4 * 8) = uh;
        }
        __syncthreads();

        {
            const int gn = gt + NBLK;
            if (gn < NTILES) {
                const float4* src = (const float4*)(neigh + (size_t)gn * (ROWS_T * FF));
#pragma unroll
                for (int u = 0; u < 16; ++u) {
                    int idx = tid + u * 256;
                    if (idx < NSTG4) cp_async16(sb + SM_STG + idx * 16, src + idx);
                }
            }
            CP_COMMIT();
        }

        float acc[2][16][4];
#pragma unroll
        for (int mt = 0; mt < 2; ++mt)
#pragma unroll
            for (int nt = 0; nt < 16; ++nt)
#pragma unroll
                for (int i = 0; i < 4; ++i) acc[mt][nt][i] = 0.f;

#pragma unroll
        for (int s = 0; s < 8; ++s) {
            u32 ah[2][4];
#pragma unroll
            for (int mt = 0; mt < 2; ++mt) {
                u32 off = (u32)((m0 + mt * 16 + a_row_l) * ASTR + (s * 16 + a_koff) * 2);
                ldsm4(sb + SM_AHI + off, ah[mt][0], ah[mt][1], ah[mt][2], ah[mt][3]);
            }
#pragma unroll
            for (int nt2 = 0; nt2 < 8; ++nt2) {
                u32 bh[4];
                u32 boff = (u32)((s * 16 + a_row_l) * BSTR + (n0 + nt2 * 16 + a_koff) * 2);
                ldsm4t(sb + SM_B + boff, bh[0], bh[1], bh[2], bh[3]);
#pragma unroll
                for (int mt = 0; mt < 2; ++mt) {
                    mma16816h(acc[mt][nt2 * 2],     ah[mt], bh[0], bh[1]);
                    mma16816h(acc[mt][nt2 * 2 + 1], ah[mt], bh[2], bh[3]);
                }
            }
        }
        __syncthreads();

#pragma unroll
        for (int mt = 0; mt < 2; ++mt)
#pragma unroll
            for (int nt = 0; nt < 16; ++nt) {
                const int row = m0 + mt * 16 + g8;
                const int col = n0 + nt * 8 + tig * 2;
                u32 p0, p1;
                asm("cvt.rn.f16x2.f32 %0, %1, %2;" : "=r"(p0)
                    : "f"(acc[mt][nt][1]), "f"(acc[mt][nt][0]));
                asm("cvt.rn.f16x2.f32 %0, %1, %2;" : "=r"(p1)
                    : "f"(acc[mt][nt][3]), "f"(acc[mt][nt][2]));
                *(u32*)(smem + row * 528 + col * 2) = p0;
                *(u32*)(smem + (row + 8) * 528 + col * 2) = p1;
            }
        __syncthreads();

        {
            const float g1v = __ldg(&g1[tid]);
            const __half* zc = (const __half*)smem + tid;
#pragma unroll
            for (int grp = 0; grp < 5; ++grp) {
                const __half* zb = zc + grp * 25 * ZHSTR;
                float mx = -3.4e38f, mn = 3.4e38f;
#pragma unroll
                for (int r = 0; r < 25; ++r) {
                    float v = __half2float(zb[r * ZHSTR]);
                    mx = fmaxf(mx, v);
                    mn = fminf(mn, v);
                    sAcc += v;
                    qAcc = fmaf(v, v, qAcc);
                }
                d_poolZ[(size_t)(5 * gt + grp) * TT + tid] = (g1v >= 0.f) ? mx : mn;
            }
        }
        __syncthreads();
    }

    d_pBs2[blockIdx.x * 256 + tid] = sAcc;
    d_pBq2[blockIdx.x * 256 + tid] = qAcc;
}

// ---------------- stats1 ----------------
__global__ void __launch_bounds__(128, 1)
stats1(const float* __restrict__ g1, const float* __restrict__ b1) {
    __shared__ double ss[128], qq[128];
    const int c = blockIdx.x;
    const int t = threadIdx.x;
    double s = 0.0, q = 0.0;
    for (int i = t; i < NBLK; i += 128) {
        s += (double)d_pBs2[i * 256 + c];
        q += (double)d_pBq2[i * 256 + c];
    }
    ss[t] = s; qq[t] = q;
    __syncthreads();
#pragma unroll
    for (int w = 64; w >= 1; w >>= 1) {
        if (t < w) { ss[t] += ss[t + w]; qq[t] += qq[t + w]; }
        __syncthreads();
    }
    if (t == 0) {
        const double inv = 1.0 / (double)NKTOT;
        const double m = ss[0] * inv;
        const double var = qq[0] * inv - m * m;
        const float a = g1[c] * rsqrtf((float)var + EPSB);
        d_a1[c] = a;
        d_c1[c] = b1[c] - a * (float)m;
    }
}

// ---------------- pass C1: SW = self @ Ws, cp.async double-buffered ----------------
__global__ void __launch_bounds__(256, 1)
passC1(const float* __restrict__ selfn, const float* __restrict__ Ws) {
    __shared__ float sm[2048];
    const u32 sb = smem_u32(sm);
    const int tid = threadIdx.x;
    const int grp = tid >> 7;
    const int j = tid & 127;
    const int bid = blockIdx.x;
    const int stride = C1NB * 8;

    u64 w2[64];
#pragma unroll
    for (int i = 0; i < 64; ++i)
        w2[i] = pack2(Ws[(2 * i) * OUTD + j], Ws[(2 * i + 1) * OUTD + j]);

    {
        const float4* src = (const float4*)(selfn + (size_t)bid * 8 * FF);
        cp_async16(sb + tid * 16, src + tid);
        CP_COMMIT();
    }
    int cur = 0;
    float s = 0.f, q = 0.f;
    for (int base = bid * 8; base < NN; base += stride) {
        CP_WAIT0();
        __syncthreads();
        {
            const int nb = base + stride;
            if (nb < NN) {
                const float4* src = (const float4*)(selfn + (size_t)nb * FF);
                cp_async16(sb + (cur ^ 1) * 4096 + tid * 16, src + tid);
            }
            CP_COMMIT();
        }
        const float* xs = sm + cur * 1024;
#pragma unroll
        for (int ndp = 0; ndp < 2; ++ndp) {
            const int r0 = grp * 4 + ndp * 2;
            const ulonglong2* x0 = (const ulonglong2*)(xs + r0 * FF);
            const ulonglong2* x1 = (const ulonglong2*)(xs + (r0 + 1) * FF);
            u64 a0 = 0ull, a1 = 0ull, b0 = 0ull, b1 = 0ull;
#pragma unroll
            for (int i = 0; i < 32; ++i) {
                ulonglong2 v0 = x0[i];
                ulonglong2 v1 = x1[i];
                fma2(a0, v0.x, w2[2 * i]);
                fma2(a1, v0.y, w2[2 * i + 1]);
                fma2(b0, v1.x, w2[2 * i]);
                fma2(b1, v1.y, w2[2 * i + 1]);
            }
            float2 fa = unpack2(a0), fb = unpack2(a1);
            const float z0 = (fa.x + fa.y) + (fb.x + fb.y);
            fa = unpack2(b0); fb = unpack2(b1);
            const float z1 = (fa.x + fa.y) + (fb.x + fb.y);
            d_SW[(size_t)(base + r0) * OUTD + j] = z0;
            d_SW[(size_t)(base + r0 + 1) * OUTD + j] = z1;
            s += z0;
            q = fmaf(z0, z0, q);
            s += z1;
            q = fmaf(z1, z1, q);
        }
        cur ^= 1;
    }
    d_pC1s[bid * 256 + tid] = s;
    d_pC1q[bid * 256 + tid] = q;
}

// ================= pass C2h: PW = (a1*poolZ + c1) @ Wn via HMMA, mean-centered fp16 =================
__global__ void __launch_bounds__(256, 1)
passC2h(const float* __restrict__ Wn, const float* __restrict__ g1,
        const float* __restrict__ b1) {
    extern __shared__ char smem[];
    const u32 sb = smem_u32(smem);
    float* a1s  = (float*)(smem + C2AC);
    float* c1s  = a1s + 256;
    float* mus  = c1s + 256;
    float* muT  = mus + 256;
    float* muWn = muT + 256;
    float* zbuf = (float*)smem;
    const int tid = threadIdx.x;
    const int lane = tid & 31;
    const int wid = tid >> 5;
    const int g8 = lane >> 2;
    const int tig = lane & 3;
    const int m0 = (wid & 3) * 32;
    const int n0 = (wid >> 2) * 64;
    const int a_row_l = lane & 15;
    const int a_koff = (lane >> 4) << 3;
    const int jj = tid & 127;
    const int hh = tid >> 7;

    // a1/c1/mu into smem. mu_t = E[pooled_t] = 1.966*|g1| + b1 (max-of-25-std-normals mean)
    a1s[tid] = d_a1[tid];
    c1s[tid] = d_c1[tid];
    mus[tid] = 1.966f * fabsf(g1[tid]) + b1[tid];

    // B = fp16(Wn): 256 k-rows x 128 cols
    for (int idx = tid; idx < 8192; idx += 256) {
        int k = idx >> 5, j4 = idx & 31;
        float4 v = ((const float4*)Wn)[idx];
        uint2 uh;
        asm("cvt.rn.f16x2.f32 %0, %1, %2;" : "=r"(uh.x) : "f"(v.y), "f"(v.x));
        asm("cvt.rn.f16x2.f32 %0, %1, %2;" : "=r"(uh.y) : "f"(v.w), "f"(v.z));
        *(uint2*)(smem + C2B + k * 272 + j4 * 8) = uh;
    }
    __syncthreads();

    // muWn[j] = sum_t mu[t] * Wn[t][j]  (exact f32 correction added back post-GEMM)
    {
        float p = 0.f;
        const int t0 = hh * 128;
        for (int t = 0; t < 128; ++t)
            p += mus[t0 + t] * Wn[(t0 + t) * OUTD + jj];
        muT[tid] = p;
    }
    __syncthreads();
    if (tid < 128) muWn[tid] = muT[tid] + muT[tid + 128];
    __syncthreads();

    float sAcc = 0.f, qAcc = 0.f;

    for (int tile = blockIdx.x; tile < NTL2; tile += C2NB) {
        __syncthreads();   // prev tile's zbuf readers done before A overwrite

        // ---- convert pooled -> centered fp16 A with BN1 affine folded ----
        for (int idx = tid; idx < 8192; idx += 256) {
            int r = idx >> 6, t4 = idx & 63;
            int node = tile * 128 + r;
            float4 x;
            if (node < NN) {
                float4 v = ((const float4*)(d_poolZ + (size_t)node * TT))[t4];
                float4 a = ((const float4*)a1s)[t4];
                float4 c = ((const float4*)c1s)[t4];
                float4 m = ((const float4*)mus)[t4];
                x.x = fmaf(a.x, v.x, c.x) - m.x;
                x.y = fmaf(a.y, v.y, c.y) - m.y;
                x.z = fmaf(a.z, v.z, c.z) - m.z;
                x.w = fmaf(a.w, v.w, c.w) - m.w;
            } else {
                x = make_float4(0.f, 0.f, 0.f, 0.f);
            }
            uint2 uh;
            asm("cvt.rn.f16x2.f32 %0, %1, %2;" : "=r"(uh.x) : "f"(x.y), "f"(x.x));
            asm("cvt.rn.f16x2.f32 %0, %1, %2;" : "=r"(uh.y) : "f"(x.w), "f"(x.z));
            *(uint2*)(smem + C2A + r * 528 + t4 * 8) = uh;
        }
        __syncthreads();

        // ---- MMA: 128x128 tile, K=256 ----
        float acc[2][8][4];
#pragma unroll
        for (int mt = 0; mt < 2; ++mt)
#pragma unroll
            for (int nt = 0; nt < 8; ++nt)
#pragma unroll
                for (int i = 0; i < 4; ++i) acc[mt][nt][i] = 0.f;

#pragma unroll
        for (int s = 0; s < 16; ++s) {
            u32 ah[2][4];
#pragma unroll
            for (int mt = 0; mt < 2; ++mt) {
                u32 off = (u32)((m0 + mt * 16 + a_row_l) * 528 + (s * 16 + a_koff) * 2);
                ldsm4(sb + C2A + off, ah[mt][0], ah[mt][1], ah[mt][2], ah[mt][3]);
            }
#pragma unroll
            for (int nt2 = 0; nt2 < 4; ++nt2) {
                u32 bh[4];
                u32 boff = (u32)((s * 16 + a_row_l) * 272 + (n0 + nt2 * 16 + a_koff) * 2);
                ldsm4t(sb + C2B + boff, bh[0], bh[1], bh[2], bh[3]);
#pragma unroll
                for (int mt = 0; mt < 2; ++mt) {
                    mma16816h(acc[mt][nt2 * 2],     ah[mt], bh[0], bh[1]);
                    mma16816h(acc[mt][nt2 * 2 + 1], ah[mt], bh[2], bh[3]);
                }
            }
        }
        __syncthreads();   // A reads done before zbuf (aliases A) writes

        // ---- fragments -> zbuf f32 ----
#pragma unroll
        for (int mt = 0; mt < 2; ++mt)
#pragma unroll
            for (int nt = 0; nt < 8; ++nt) {
                const int row = m0 + mt * 16 + g8;
                const int col = n0 + nt * 8 + tig * 2;
                float2 lo2; lo2.x = acc[mt][nt][0]; lo2.y = acc[mt][nt][1];
                float2 hi2; hi2.x = acc[mt][nt][2]; hi2.y = acc[mt][nt][3];
                *(float2*)(zbuf + row * ZST2 + col) = lo2;
                *(float2*)(zbuf + (row + 8) * ZST2 + col) = hi2;
            }
        __syncthreads();

        // ---- column sums with +muWn correction + coalesced PW writes ----
        {
            const float mw = muWn[jj];
            const int rbase = tile * 128 + hh * 64;
#pragma unroll
            for (int rr = 0; rr < 64; ++rr) {
                if (rbase + rr < NN) {
                    float v = zbuf[(hh * 64 + rr) * ZST2 + jj] + mw;
                    sAcc += v;
                    qAcc = fmaf(v, v, qAcc);
                }
            }
        }
        for (int idx = tid; idx < 4096; idx += 256) {
            int r = idx >> 5, c4 = idx & 31;
            int grow = tile * 128 + r;
            if (grow < NN) {
                float4 v = *(const float4*)(zbuf + r * ZST2 + c4 * 4);
                float4 mw4 = ((const float4*)muWn)[c4];
                v.x += mw4.x; v.y += mw4.y; v.z += mw4.z; v.w += mw4.w;
                ((float4*)(d_PW + (size_t)grow * OUTD))[c4] = v;
            }
        }
    }

    d_pC2s[blockIdx.x * 256 + tid] = sAcc;
    d_pC2q[blockIdx.x * 256 + tid] = qAcc;
}

// ---------------- stats2 ----------------
__global__ void __launch_bounds__(128, 1)
stats2(const float* __restrict__ g2, const float* __restrict__ b2) {
    __shared__ double ss[128], qq[128];
    const int c = blockIdx.x;
    const int t = threadIdx.x;
    double s = 0.0, q = 0.0;
    if (c < 128) {
        for (int i = t; i < C1NB * 2; i += 128) {
            const int b = i >> 1, off = (i & 1) * 128;
            s += (double)d_pC1s[b * 256 + off + c];
            q += (double)d_pC1q[b * 256 + off + c];
        }
    } else {
        const int jr = c - 128;
        for (int i = t; i < C2NB * 2; i += 128) {
            const int b = i >> 1, off = (i & 1) * 128;
            s += (double)d_pC2s[b * 256 + off + jr];
            q += (double)d_pC2q[b * 256 + off + jr];
        }
    }
    ss[t] = s; qq[t] = q;
    __syncthreads();
#pragma unroll
    for (int w = 64; w >= 1; w >>= 1) {
        if (t < w) { ss[t] += ss[t + w]; qq[t] += qq[t + w]; }
        __syncthreads();
    }
    if (t == 0) {
        const double inv = 1.0 / (double)NN;
        const double m = ss[0] * inv;
        const double var = qq[0] * inv - m * m;
        const float a = g2[c] * rsqrtf((float)var + EPSB);
        d_a2[c] = a;
        d_c2[c] = b2[c] - a * (float)m;
    }
}

// ---------------- pass E ----------------
__global__ void passE(float* __restrict__ out) {
    const int base = (blockIdx.x * blockDim.x + threadIdx.x) * 4;
#pragma unroll
    for (int u = 0; u < 4; ++u) {
        const int idx = base + u;
        if (idx >= NN * 64) return;
        const int n = idx >> 6;
        const int c4 = idx & 63;
        float4 v;
        if (c4 < 32) v = ((const float4*)d_SW)[(size_t)n * 32 + c4];
        else         v = ((const float4*)d_PW)[(size_t)n * 32 + (c4 - 32)];
        const float4 a = ((const float4*)d_a2)[c4];
        const float4 c = ((const float4*)d_c2)[c4];
        float4 r;
        r.x = fmaxf(0.f, fmaf(a.x, v.x, c.x));
        r.y = fmaxf(0.f, fmaf(a.y, v.y, c.y));
        r.z = fmaxf(0.f, fmaf(a.z, v.z, c.z));
        r.w = fmaxf(0.f, fmaf(a.w, v.w, c.w));
        ((float4*)out)[idx] = r;
    }
}

// ---------------- launch ----------------
extern "C" void kernel_launch(void* const* d_in, const int* in_sizes, int n_in,
                              void* d_out, int out_size) {
    const float* selfn = (const float*)d_in[0];
    const float* neigh = (const float*)d_in[1];
    const float* Wt = (const float*)d_in[3];
    const float* g1 = (const float*)d_in[5];
    const float* b1 = (const float*)d_in[6];
    const float* Wn = (const float*)d_in[7];
    const float* Ws = (const float*)d_in[8];
    const float* g2 = (const float*)d_in[9];
    const float* b2 = (const float*)d_in[10];
    float* out = (float*)d_out;

    static int configured = 0;
    if (!configured) {
        cudaFuncSetAttribute(passB, cudaFuncAttributeMaxDynamicSharedMemorySize, SM_TOTAL);
        cudaFuncSetAttribute(passC2h, cudaFuncAttributeMaxDynamicSharedMemorySize, SM2_TOTAL);
        configured = 1;
    }

    passB<<<NBLK, 256, SM_TOTAL>>>(neigh, Wt, g1);
    stats1<<<256, 128>>>(g1, b1);
    passC1<<<C1NB, 256>>>(selfn, Ws);
    passC2h<<<C2NB, 256, SM2_TOTAL>>>(Wn, g1, b1);
    stats2<<<256, 128>>>(g2, b2);
    passE<<<(NN * 64 + 1023) / 1024, 256>>>(out);
}

// round 16
// speedup vs baseline: 1.5509x; 1.5509x over previous
#include <cuda_runtime.h>
#include <cuda_fp16.h>
#include <cstdint>

#define NN   50000
#define KK   25
#define FF   128
#define TT   256
#define OUTD 128
#define NBLK 148
#define NKTOT 1250000
#define EPSB 1e-3f
#define NTILES (NN / 5)          /* 10000 */
#define ROWS_T 125               /* 5 nodes * 25 */
#define C1NB 148
#define C2NB 148
#define NSTG4 4000
#define NTL2 391                 /* ceil(50000/128) */

typedef unsigned long long u64;
typedef unsigned int u32;

// ---------------- smem layout for passB ----------------
#define SM_AHI  0
#define SM_B    69632
#define SM_STG  137216
#define SM_TOTAL (137216 + 64000)   /* 201216 */
#define ASTR 272
#define BSTR 528
#define ZHSTR 264

// ---------------- smem layout for passC2h ----------------
#define C2A   0                     /* A fp16: 128 rows x 528B = 67584; zbuf f32 128x132 aliases */
#define C2B   67584                 /* B fp16: 256 rows x 272B = 69632 */
#define C2AC  137216                /* a1s/c1s (512 floats) + muWn (128 floats) */
#define SM2_TOTAL (137216 + 2560)   /* 139776 */
#define ZST2  132

// ---------------- scratch ----------------
__device__ float d_poolZ[(size_t)NN * TT];
__device__ float d_SW[(size_t)NN * OUTD];
__device__ float d_PW[(size_t)NN * OUTD];
__device__ float d_pBs2[NBLK * 256];
__device__ float d_pBq2[NBLK * 256];
__device__ float d_pC1s[C1NB * 256];
__device__ float d_pC1q[C1NB * 256];
__device__ float d_pC2s[C2NB * 256];
__device__ float d_pC2q[C2NB * 256];
__device__ float d_a1[TT], d_c1[TT];
__device__ float d_a2[256], d_c2[256];
__device__ float d_muWn[128];

// ---------------- helpers ----------------
__device__ __forceinline__ u32 smem_u32(const void* p) {
    u32 a;
    asm("{ .reg .u64 t; cvta.to.shared.u64 t, %1; cvt.u32.u64 %0, t; }" : "=r"(a) : "l"(p));
    return a;
}
__device__ __forceinline__ void ldsm4(u32 a, u32& r0, u32& r1, u32& r2, u32& r3) {
    asm volatile("ldmatrix.sync.aligned.m8n8.x4.shared.b16 {%0,%1,%2,%3}, [%4];"
                 : "=r"(r0), "=r"(r1), "=r"(r2), "=r"(r3) : "r"(a));
}
__device__ __forceinline__ void ldsm4t(u32 a, u32& r0, u32& r1, u32& r2, u32& r3) {
    asm volatile("ldmatrix.sync.aligned.m8n8.x4.trans.shared.b16 {%0,%1,%2,%3}, [%4];"
                 : "=r"(r0), "=r"(r1), "=r"(r2), "=r"(r3) : "r"(a));
}
__device__ __forceinline__ void mma16816h(float* d, const u32* a, u32 b0, u32 b1) {
    asm volatile(
        "mma.sync.aligned.m16n8k16.row.col.f32.f16.f16.f32 "
        "{%0,%1,%2,%3}, {%4,%5,%6,%7}, {%8,%9}, {%0,%1,%2,%3};"
        : "+f"(d[0]), "+f"(d[1]), "+f"(d[2]), "+f"(d[3])
        : "r"(a[0]), "r"(a[1]), "r"(a[2]), "r"(a[3]), "r"(b0), "r"(b1));
}
__device__ __forceinline__ u64 pack2(float lo, float hi) {
    u64 r;
    asm("mov.b64 %0, {%1, %2};" : "=l"(r) : "f"(lo), "f"(hi));
    return r;
}
__device__ __forceinline__ void fma2(u64& acc, u64 a, u64 b) {
    asm("fma.rn.f32x2 %0, %1, %2, %0;" : "+l"(acc) : "l"(a), "l"(b));
}
__device__ __forceinline__ float2 unpack2(u64 v) {
    float lo, hi;
    asm("mov.b64 {%0, %1}, %2;" : "=f"(lo), "=f"(hi) : "l"(v));
    return make_float2(lo, hi);
}
__device__ __forceinline__ void cp_async16(u32 dst, const void* src) {
    asm volatile("cp.async.cg.shared.global [%0], [%1], 16;" :: "r"(dst), "l"(src));
}
#define CP_COMMIT() asm volatile("cp.async.commit_group;" ::: "memory")
#define CP_WAIT0()  asm volatile("cp.async.wait_group 0;" ::: "memory")

// ================= pass B: byte-identical to R12/R13 =================
__global__ void __launch_bounds__(256, 1)
passB(const float* __restrict__ neigh, const float* __restrict__ Wt,
      const float* __restrict__ g1) {
    extern __shared__ char smem[];
    const u32 sb = smem_u32(smem);
    const int tid = threadIdx.x;
    const int lane = tid & 31;
    const int wid = tid >> 5;
    const int g8 = lane >> 2;
    const int tig = lane & 3;
    const int mwarp = wid & 3;
    const int nwarp = wid >> 2;
    const int m0 = mwarp * 32;
    const int n0 = nwarp * 128;
    const float4* stg4 = (const float4*)(smem + SM_STG);

    {
        const float4* src = (const float4*)(neigh + (size_t)blockIdx.x * (ROWS_T * FF));
#pragma unroll
        for (int u = 0; u < 16; ++u) {
            int idx = tid + u * 256;
            if (idx < NSTG4) cp_async16(sb + SM_STG + idx * 16, src + idx);
        }
        CP_COMMIT();
    }

    for (int idx = tid; idx < FF * 64; idx += 256) {
        int k = idx >> 6, n4 = idx & 63;
        float4 v = ((const float4*)Wt)[idx];
        uint2 uh;
        asm("cvt.rn.f16x2.f32 %0, %1, %2;" : "=r"(uh.x) : "f"(v.y), "f"(v.x));
        asm("cvt.rn.f16x2.f32 %0, %1, %2;" : "=r"(uh.y) : "f"(v.w), "f"(v.z));
        *(uint2*)(smem + SM_B + k * BSTR + n4 * 8) = uh;
    }

    const int a_row_l = lane & 15;
    const int a_koff  = (lane >> 4) << 3;
    float sAcc = 0.f, qAcc = 0.f;

    for (int gt = blockIdx.x; gt < NTILES; gt += NBLK) {
        CP_WAIT0();
        __syncthreads();

        for (int idx = tid; idx < NSTG4; idx += 256) {
            float4 v = stg4[idx];
            int r = idx >> 5, c4 = idx & 31;
            uint2 uh;
            asm("cvt.rn.f16x2.f32 %0, %1, %2;" : "=r"(uh.x) : "f"(v.y), "f"(v.x));
            asm("cvt.rn.f16x2.f32 %0, %1, %2;" : "=r"(uh.y) : "f"(v.w), "f"(v.z));
            *(uint2*)(smem + SM_AHI + r * ASTR + c4 * 8) = uh;
        }
        __syncthreads();

        {
            const int gn = gt + NBLK;
            if (gn < NTILES) {
                const float4* src = (const float4*)(neigh + (size_t)gn * (ROWS_T * FF));
#pragma unroll
                for (int u = 0; u < 16; ++u) {
                    int idx = tid + u * 256;
                    if (idx < NSTG4) cp_async16(sb + SM_STG + idx * 16, src + idx);
                }
            }
            CP_COMMIT();
        }

        float acc[2][16][4];
#pragma unroll
        for (int mt = 0; mt < 2; ++mt)
#pragma unroll
            for (int nt = 0; nt < 16; ++nt)
#pragma unroll
                for (int i = 0; i < 4; ++i) acc[mt][nt][i] = 0.f;

#pragma unroll
        for (int s = 0; s < 8; ++s) {
            u32 ah[2][4];
#pragma unroll
            for (int mt = 0; mt < 2; ++mt) {
                u32 off = (u32)((m0 + mt * 16 + a_row_l) * ASTR + (s * 16 + a_koff) * 2);
                ldsm4(sb + SM_AHI + off, ah[mt][0], ah[mt][1], ah[mt][2], ah[mt][3]);
            }
#pragma unroll
            for (int nt2 = 0; nt2 < 8; ++nt2) {
                u32 bh[4];
                u32 boff = (u32)((s * 16 + a_row_l) * BSTR + (n0 + nt2 * 16 + a_koff) * 2);
                ldsm4t(sb + SM_B + boff, bh[0], bh[1], bh[2], bh[3]);
#pragma unroll
                for (int mt = 0; mt < 2; ++mt) {
                    mma16816h(acc[mt][nt2 * 2],     ah[mt], bh[0], bh[1]);
                    mma16816h(acc[mt][nt2 * 2 + 1], ah[mt], bh[2], bh[3]);
                }
            }
        }
        __syncthreads();

#pragma unroll
        for (int mt = 0; mt < 2; ++mt)
#pragma unroll
            for (int nt = 0; nt < 16; ++nt) {
                const int row = m0 + mt * 16 + g8;
                const int col = n0 + nt * 8 + tig * 2;
                u32 p0, p1;
                asm("cvt.rn.f16x2.f32 %0, %1, %2;" : "=r"(p0)
                    : "f"(acc[mt][nt][1]), "f"(acc[mt][nt][0]));
                asm("cvt.rn.f16x2.f32 %0, %1, %2;" : "=r"(p1)
                    : "f"(acc[mt][nt][3]), "f"(acc[mt][nt][2]));
                *(u32*)(smem + row * 528 + col * 2) = p0;
                *(u32*)(smem + (row + 8) * 528 + col * 2) = p1;
            }
        __syncthreads();

        {
            const float g1v = __ldg(&g1[tid]);
            const __half* zc = (const __half*)smem + tid;
#pragma unroll
            for (int grp = 0; grp < 5; ++grp) {
                const __half* zb = zc + grp * 25 * ZHSTR;
                float mx = -3.4e38f, mn = 3.4e38f;
#pragma unroll
                for (int r = 0; r < 25; ++r) {
                    float v = __half2float(zb[r * ZHSTR]);
                    mx = fmaxf(mx, v);
                    mn = fminf(mn, v);
                    sAcc += v;
                    qAcc = fmaf(v, v, qAcc);
                }
                d_poolZ[(size_t)(5 * gt + grp) * TT + tid] = (g1v >= 0.f) ? mx : mn;
            }
        }
        __syncthreads();
    }

    d_pBs2[blockIdx.x * 256 + tid] = sAcc;
    d_pBq2[blockIdx.x * 256 + tid] = qAcc;
}

// ---------------- stats1 ----------------
__global__ void __launch_bounds__(128, 1)
stats1(const float* __restrict__ g1, const float* __restrict__ b1) {
    __shared__ double ss[128], qq[128];
    const int c = blockIdx.x;
    const int t = threadIdx.x;
    double s = 0.0, q = 0.0;
    for (int i = t; i < NBLK; i += 128) {
        s += (double)d_pBs2[i * 256 + c];
        q += (double)d_pBq2[i * 256 + c];
    }
    ss[t] = s; qq[t] = q;
    __syncthreads();
#pragma unroll
    for (int w = 64; w >= 1; w >>= 1) {
        if (t < w) { ss[t] += ss[t + w]; qq[t] += qq[t + w]; }
        __syncthreads();
    }
    if (t == 0) {
        const double inv = 1.0 / (double)NKTOT;
        const double m = ss[0] * inv;
        const double var = qq[0] * inv - m * m;
        const float a = g1[c] * rsqrtf((float)var + EPSB);
        d_a1[c] = a;
        d_c1[c] = b1[c] - a * (float)m;
    }
}

// ---------------- muWnK: muWn[j] = sum_t mu[t]*Wn[t][j], one block per column ----------------
__global__ void __launch_bounds__(256, 1)
muWnK(const float* __restrict__ Wn, const float* __restrict__ g1,
      const float* __restrict__ b1) {
    __shared__ float red[256];
    const int j = blockIdx.x;    // 0..127
    const int t = threadIdx.x;   // 0..255
    const float mu = 1.966f * fabsf(g1[t]) + b1[t];
    red[t] = mu * Wn[t * OUTD + j];
    __syncthreads();
#pragma unroll
    for (int w = 128; w >= 1; w >>= 1) {
        if (t < w) red[t] += red[t + w];
        __syncthreads();
    }
    if (t == 0) d_muWn[j] = red[0];
}

// ---------------- pass C1: SW = self @ Ws, cp.async double-buffered ----------------
__global__ void __launch_bounds__(256, 1)
passC1(const float* __restrict__ selfn, const float* __restrict__ Ws) {
    __shared__ float sm[2048];
    const u32 sb = smem_u32(sm);
    const int tid = threadIdx.x;
    const int grp = tid >> 7;
    const int j = tid & 127;
    const int bid = blockIdx.x;
    const int stride = C1NB * 8;

    u64 w2[64];
#pragma unroll
    for (int i = 0; i < 64; ++i)
        w2[i] = pack2(Ws[(2 * i) * OUTD + j], Ws[(2 * i + 1) * OUTD + j]);

    {
        const float4* src = (const float4*)(selfn + (size_t)bid * 8 * FF);
        cp_async16(sb + tid * 16, src + tid);
        CP_COMMIT();
    }
    int cur = 0;
    float s = 0.f, q = 0.f;
    for (int base = bid * 8; base < NN; base += stride) {
        CP_WAIT0();
        __syncthreads();
        {
            const int nb = base + stride;
            if (nb < NN) {
                const float4* src = (const float4*)(selfn + (size_t)nb * FF);
                cp_async16(sb + (cur ^ 1) * 4096 + tid * 16, src + tid);
            }
            CP_COMMIT();
        }
        const float* xs = sm + cur * 1024;
#pragma unroll
        for (int ndp = 0; ndp < 2; ++ndp) {
            const int r0 = grp * 4 + ndp * 2;
            const ulonglong2* x0 = (const ulonglong2*)(xs + r0 * FF);
            const ulonglong2* x1 = (const ulonglong2*)(xs + (r0 + 1) * FF);
            u64 a0 = 0ull, a1 = 0ull, b0 = 0ull, b1 = 0ull;
#pragma unroll
            for (int i = 0; i < 32; ++i) {
                ulonglong2 v0 = x0[i];
                ulonglong2 v1 = x1[i];
                fma2(a0, v0.x, w2[2 * i]);
                fma2(a1, v0.y, w2[2 * i + 1]);
                fma2(b0, v1.x, w2[2 * i]);
                fma2(b1, v1.y, w2[2 * i + 1]);
            }
            float2 fa = unpack2(a0), fb = unpack2(a1);
            const float z0 = (fa.x + fa.y) + (fb.x + fb.y);
            fa = unpack2(b0); fb = unpack2(b1);
            const float z1 = (fa.x + fa.y) + (fb.x + fb.y);
            d_SW[(size_t)(base + r0) * OUTD + j] = z0;
            d_SW[(size_t)(base + r0 + 1) * OUTD + j] = z1;
            s += z0;
            q = fmaf(z0, z0, q);
            s += z1;
            q = fmaf(z1, z1, q);
        }
        cur ^= 1;
    }
    d_pC1s[bid * 256 + tid] = s;
    d_pC1q[bid * 256 + tid] = q;
}

// ================= pass C2h: PW = (a1*poolZ + c1) @ Wn via HMMA, centered (mu folded into c1) =================
__global__ void __launch_bounds__(256, 1)
passC2h(const float* __restrict__ Wn, const float* __restrict__ g1,
        const float* __restrict__ b1) {
    extern __shared__ char smem[];
    const u32 sb = smem_u32(smem);
    float* a1s  = (float*)(smem + C2AC);
    float* c1s  = a1s + 256;
    float* muWn = c1s + 256;
    float* zbuf = (float*)smem;
    const int tid = threadIdx.x;
    const int lane = tid & 31;
    const int wid = tid >> 5;
    const int g8 = lane >> 2;
    const int tig = lane & 3;
    const int m0 = (wid & 3) * 32;
    const int n0 = (wid >> 2) * 64;
    const int a_row_l = lane & 15;
    const int a_koff = (lane >> 4) << 3;
    const int jj = tid & 127;
    const int hh = tid >> 7;

    // a1 and centered c1 into smem: c1' = c1 - mu, mu = 1.966*|g1| + b1
    a1s[tid] = d_a1[tid];
    c1s[tid] = d_c1[tid] - (1.966f * fabsf(g1[tid]) + b1[tid]);
    if (tid < 128) muWn[tid] = d_muWn[tid];

    // B = fp16(Wn): 256 k-rows x 128 cols
    for (int idx = tid; idx < 8192; idx += 256) {
        int k = idx >> 5, j4 = idx & 31;
        float4 v = ((const float4*)Wn)[idx];
        uint2 uh;
        asm("cvt.rn.f16x2.f32 %0, %1, %2;" : "=r"(uh.x) : "f"(v.y), "f"(v.x));
        asm("cvt.rn.f16x2.f32 %0, %1, %2;" : "=r"(uh.y) : "f"(v.w), "f"(v.z));
        *(uint2*)(smem + C2B + k * 272 + j4 * 8) = uh;
    }
    __syncthreads();

    float sAcc = 0.f, qAcc = 0.f;

    for (int tile = blockIdx.x; tile < NTL2; tile += C2NB) {
        __syncthreads();   // prev tile's zbuf readers done before A overwrite

        // ---- convert pooled -> centered fp16 A (same cost as R13) ----
        for (int idx = tid; idx < 8192; idx += 256) {
            int r = idx >> 6, t4 = idx & 63;
            int node = tile * 128 + r;
            float4 x;
            if (node < NN) {
                float4 v = ((const float4*)(d_poolZ + (size_t)node * TT))[t4];
                float4 a = ((const float4*)a1s)[t4];
                float4 c = ((const float4*)c1s)[t4];
                x.x = fmaf(a.x, v.x, c.x);
                x.y = fmaf(a.y, v.y, c.y);
                x.z = fmaf(a.z, v.z, c.z);
                x.w = fmaf(a.w, v.w, c.w);
            } else {
                x = make_float4(0.f, 0.f, 0.f, 0.f);
            }
            uint2 uh;
            asm("cvt.rn.f16x2.f32 %0, %1, %2;" : "=r"(uh.x) : "f"(x.y), "f"(x.x));
            asm("cvt.rn.f16x2.f32 %0, %1, %2;" : "=r"(uh.y) : "f"(x.w), "f"(x.z));
            *(uint2*)(smem + C2A + r * 528 + t4 * 8) = uh;
        }
        __syncthreads();

        // ---- MMA: 128x128 tile, K=256 ----
        float acc[2][8][4];
#pragma unroll
        for (int mt = 0; mt < 2; ++mt)
#pragma unroll
            for (int nt = 0; nt < 8; ++nt)
#pragma unroll
                for (int i = 0; i < 4; ++i) acc[mt][nt][i] = 0.f;

#pragma unroll
        for (int s = 0; s < 16; ++s) {
            u32 ah[2][4];
#pragma unroll
            for (int mt = 0; mt < 2; ++mt) {
                u32 off = (u32)((m0 + mt * 16 + a_row_l) * 528 + (s * 16 + a_koff) * 2);
                ldsm4(sb + C2A + off, ah[mt][0], ah[mt][1], ah[mt][2], ah[mt][3]);
            }
#pragma unroll
            for (int nt2 = 0; nt2 < 4; ++nt2) {
                u32 bh[4];
                u32 boff = (u32)((s * 16 + a_row_l) * 272 + (n0 + nt2 * 16 + a_koff) * 2);
                ldsm4t(sb + C2B + boff, bh[0], bh[1], bh[2], bh[3]);
#pragma unroll
                for (int mt = 0; mt < 2; ++mt) {
                    mma16816h(acc[mt][nt2 * 2],     ah[mt], bh[0], bh[1]);
                    mma16816h(acc[mt][nt2 * 2 + 1], ah[mt], bh[2], bh[3]);
                }
            }
        }
        __syncthreads();   // A reads done before zbuf (aliases A) writes

        // ---- fragments -> zbuf f32 ----
#pragma unroll
        for (int mt = 0; mt < 2; ++mt)
#pragma unroll
            for (int nt = 0; nt < 8; ++nt) {
                const int row = m0 + mt * 16 + g8;
                const int col = n0 + nt * 8 + tig * 2;
                float2 lo2; lo2.x = acc[mt][nt][0]; lo2.y = acc[mt][nt][1];
                float2 hi2; hi2.x = acc[mt][nt][2]; hi2.y = acc[mt][nt][3];
                *(float2*)(zbuf + row * ZST2 + col) = lo2;
                *(float2*)(zbuf + (row + 8) * ZST2 + col) = hi2;
            }
        __syncthreads();

        // ---- column sums with +muWn correction + coalesced PW writes ----
        {
            const float mw = muWn[jj];
            const int rbase = tile * 128 + hh * 64;
#pragma unroll
            for (int rr = 0; rr < 64; ++rr) {
                if (rbase + rr < NN) {
                    float v = zbuf[(hh * 64 + rr) * ZST2 + jj] + mw;
                    sAcc += v;
                    qAcc = fmaf(v, v, qAcc);
                }
            }
        }
        for (int idx = tid; idx < 4096; idx += 256) {
            int r = idx >> 5, c4 = idx & 31;
            int grow = tile * 128 + r;
            if (grow < NN) {
                float4 v = *(const float4*)(zbuf + r * ZST2 + c4 * 4);
                float4 mw4 = ((const float4*)muWn)[c4];
                v.x += mw4.x; v.y += mw4.y; v.z += mw4.z; v.w += mw4.w;
                ((float4*)(d_PW + (size_t)grow * OUTD))[c4] = v;
            }
        }
    }

    d_pC2s[blockIdx.x * 256 + tid] = sAcc;
    d_pC2q[blockIdx.x * 256 + tid] = qAcc;
}

// ---------------- stats2 ----------------
__global__ void __launch_bounds__(128, 1)
stats2(const float* __restrict__ g2, const float* __restrict__ b2) {
    __shared__ double ss[128], qq[128];
    const int c = blockIdx.x;
    const int t = threadIdx.x;
    double s = 0.0, q = 0.0;
    if (c < 128) {
        for (int i = t; i < C1NB * 2; i += 128) {
            const int b = i >> 1, off = (i & 1) * 128;
            s += (double)d_pC1s[b * 256 + off + c];
            q += (double)d_pC1q[b * 256 + off + c];
        }
    } else {
        const int jr = c - 128;
        for (int i = t; i < C2NB * 2; i += 128) {
            const int b = i >> 1, off = (i & 1) * 128;
            s += (double)d_pC2s[b * 256 + off + jr];
            q += (double)d_pC2q[b * 256 + off + jr];
        }
    }
    ss[t] = s; qq[t] = q;
    __syncthreads();
#pragma unroll
    for (int w = 64; w >= 1; w >>= 1) {
        if (t < w) { ss[t] += ss[t + w]; qq[t] += qq[t + w]; }
        __syncthreads();
    }
    if (t == 0) {
        const double inv = 1.0 / (double)NN;
        const double m = ss[0] * inv;
        const double var = qq[0] * inv - m * m;
        const float a = g2[c] * rsqrtf((float)var + EPSB);
        d_a2[c] = a;
        d_c2[c] = b2[c] - a * (float)m;
    }
}

// ---------------- pass E ----------------
__global__ void passE(float* __restrict__ out) {
    const int base = (blockIdx.x * blockDim.x + threadIdx.x) * 4;
#pragma unroll
    for (int u = 0; u < 4; ++u) {
        const int idx = base + u;
        if (idx >= NN * 64) return;
        const int n = idx >> 6;
        const int c4 = idx & 63;
        float4 v;
        if (c4 < 32) v = ((const float4*)d_SW)[(size_t)n * 32 + c4];
        else         v = ((const float4*)d_PW)[(size_t)n * 32 + (c4 - 32)];
        const float4 a = ((const float4*)d_a2)[c4];
        const float4 c = ((const float4*)d_c2)[c4];
        float4 r;
        r.x = fmaxf(0.f, fmaf(a.x, v.x, c.x));
        r.y = fmaxf(0.f, fmaf(a.y, v.y, c.y));
        r.z = fmaxf(0.f, fmaf(a.z, v.z, c.z));
        r.w = fmaxf(0.f, fmaf(a.w, v.w, c.w));
        ((float4*)out)[idx] = r;
    }
}

// ---------------- launch ----------------
extern "C" void kernel_launch(void* const* d_in, const int* in_sizes, int n_in,
                              void* d_out, int out_size) {
    const float* selfn = (const float*)d_in[0];
    const float* neigh = (const float*)d_in[1];
    const float* Wt = (const float*)d_in[3];
    const float* g1 = (const float*)d_in[5];
    const float* b1 = (const float*)d_in[6];
    const float* Wn = (const float*)d_in[7];
    const float* Ws = (const float*)d_in[8];
    const float* g2 = (const float*)d_in[9];
    const float* b2 = (const float*)d_in[10];
    float* out = (float*)d_out;

    static int configured = 0;
    if (!configured) {
        cudaFuncSetAttribute(passB, cudaFuncAttributeMaxDynamicSharedMemorySize, SM_TOTAL);
        cudaFuncSetAttribute(passC2h, cudaFuncAttributeMaxDynamicSharedMemorySize, SM2_TOTAL);
        configured = 1;
    }

    passB<<<NBLK, 256, SM_TOTAL>>>(neigh, Wt, g1);
    stats1<<<256, 128>>>(g1, b1);
    muWnK<<<128, 256>>>(Wn, g1, b1);
    passC1<<<C1NB, 256>>>(selfn, Ws);
    passC2h<<<C2NB, 256, SM2_TOTAL>>>(Wn, g1, b1);
    stats2<<<256, 128>>>(g2, b2);
    passE<<<(NN * 64 + 1023) / 1024, 256>>>(out);
}

// round 17
// speedup vs baseline: 1.6356x; 1.0546x over previous
#include <cuda_runtime.h>
#include <cuda_fp16.h>
#include <cstdint>

#define NN   50000
#define KK   25
#define FF   128
#define TT   256
#define OUTD 128
#define NBLK 148
#define NKTOT 1250000
#define EPSB 1e-3f
#define NTILES (NN / 5)          /* 10000 */
#define ROWS_T 125               /* 5 nodes * 25 */
#define C1NB 148
#define C2NB 148
#define NSTG4 4000
#define NTL2 391                 /* ceil(50000/128) */

typedef unsigned long long u64;
typedef unsigned int u32;

// ---------------- smem layout for passB ----------------
#define SM_AHI  0
#define SM_B    69632
#define SM_STG  137216
#define SM_TOTAL (137216 + 64000)   /* 201216 */
#define ASTR 272
#define BSTR 528
#define ZHSTR 264

// ---------------- smem layout for passC2h ----------------
#define C2A   0                     /* A fp16: 128 rows x 528B; zbuf f32 128x132 aliases */
#define C2B   67584                 /* B fp16: 256 rows x 272B */
#define C2AC  137216                /* a1s/c1s (512 floats) + muWn (128 floats) */
#define SM2_TOTAL (137216 + 2560)   /* 139776 */
#define ZST2  132

// ---------------- smem layout for passC1h (no aliasing) ----------------
#define H1A   0                     /* A fp16: 128 rows x 272B = 34816 */
#define H1B   34816                 /* B fp16: 128 rows x 272B = 34816 */
#define H1Z   69632                 /* zbuf f32: 128 x 132 = 67584 */
#define SM1_TOTAL 137216

// ---------------- scratch ----------------
__device__ float d_poolZ[(size_t)NN * TT];
__device__ float d_SW[(size_t)NN * OUTD];
__device__ float d_PW[(size_t)NN * OUTD];
__device__ float d_pBs2[NBLK * 256];
__device__ float d_pBq2[NBLK * 256];
__device__ float d_pC1s[C1NB * 256];
__device__ float d_pC1q[C1NB * 256];
__device__ float d_pC2s[C2NB * 256];
__device__ float d_pC2q[C2NB * 256];
__device__ float d_a1[TT], d_c1[TT];
__device__ float d_a2[256], d_c2[256];
__device__ float d_muWn[128];

// ---------------- helpers ----------------
__device__ __forceinline__ u32 smem_u32(const void* p) {
    u32 a;
    asm("{ .reg .u64 t; cvta.to.shared.u64 t, %1; cvt.u32.u64 %0, t; }" : "=r"(a) : "l"(p));
    return a;
}
__device__ __forceinline__ void ldsm4(u32 a, u32& r0, u32& r1, u32& r2, u32& r3) {
    asm volatile("ldmatrix.sync.aligned.m8n8.x4.shared.b16 {%0,%1,%2,%3}, [%4];"
                 : "=r"(r0), "=r"(r1), "=r"(r2), "=r"(r3) : "r"(a));
}
__device__ __forceinline__ void ldsm4t(u32 a, u32& r0, u32& r1, u32& r2, u32& r3) {
    asm volatile("ldmatrix.sync.aligned.m8n8.x4.trans.shared.b16 {%0,%1,%2,%3}, [%4];"
                 : "=r"(r0), "=r"(r1), "=r"(r2), "=r"(r3) : "r"(a));
}
__device__ __forceinline__ void mma16816h(float* d, const u32* a, u32 b0, u32 b1) {
    asm volatile(
        "mma.sync.aligned.m16n8k16.row.col.f32.f16.f16.f32 "
        "{%0,%1,%2,%3}, {%4,%5,%6,%7}, {%8,%9}, {%0,%1,%2,%3};"
        : "+f"(d[0]), "+f"(d[1]), "+f"(d[2]), "+f"(d[3])
        : "r"(a[0]), "r"(a[1]), "r"(a[2]), "r"(a[3]), "r"(b0), "r"(b1));
}
__device__ __forceinline__ void cp_async16(u32 dst, const void* src) {
    asm volatile("cp.async.cg.shared.global [%0], [%1], 16;" :: "r"(dst), "l"(src));
}
#define CP_COMMIT() asm volatile("cp.async.commit_group;" ::: "memory")
#define CP_WAIT0()  asm volatile("cp.async.wait_group 0;" ::: "memory")

// ================= pass B: byte-identical to R12..R16 =================
__global__ void __launch_bounds__(256, 1)
passB(const float* __restrict__ neigh, const float* __restrict__ Wt,
      const float* __restrict__ g1) {
    extern __shared__ char smem[];
    const u32 sb = smem_u32(smem);
    const int tid = threadIdx.x;
    const int lane = tid & 31;
    const int wid = tid >> 5;
    const int g8 = lane >> 2;
    const int tig = lane & 3;
    const int mwarp = wid & 3;
    const int nwarp = wid >> 2;
    const int m0 = mwarp * 32;
    const int n0 = nwarp * 128;
    const float4* stg4 = (const float4*)(smem + SM_STG);

    {
        const float4* src = (const float4*)(neigh + (size_t)blockIdx.x * (ROWS_T * FF));
#pragma unroll
        for (int u = 0; u < 16; ++u) {
            int idx = tid + u * 256;
            if (idx < NSTG4) cp_async16(sb + SM_STG + idx * 16, src + idx);
        }
        CP_COMMIT();
    }

    for (int idx = tid; idx < FF * 64; idx += 256) {
        int k = idx >> 6, n4 = idx & 63;
        float4 v = ((const float4*)Wt)[idx];
        uint2 uh;
        asm("cvt.rn.f16x2.f32 %0, %1, %2;" : "=r"(uh.x) : "f"(v.y), "f"(v.x));
        asm("cvt.rn.f16x2.f32 %0, %1, %2;" : "=r"(uh.y) : "f"(v.w), "f"(v.z));
        *(uint2*)(smem + SM_B + k * BSTR + n4 * 8) = uh;
    }

    const int a_row_l = lane & 15;
    const int a_koff  = (lane >> 4) << 3;
    float sAcc = 0.f, qAcc = 0.f;

    for (int gt = blockIdx.x; gt < NTILES; gt += NBLK) {
        CP_WAIT0();
        __syncthreads();

        for (int idx = tid; idx < NSTG4; idx += 256) {
            float4 v = stg4[idx];
            int r = idx >> 5, c4 = idx & 31;
            uint2 uh;
            asm("cvt.rn.f16x2.f32 %0, %1, %2;" : "=r"(uh.x) : "f"(v.y), "f"(v.x));
            asm("cvt.rn.f16x2.f32 %0, %1, %2;" : "=r"(uh.y) : "f"(v.w), "f"(v.z));
            *(uint2*)(smem + SM_AHI + r * ASTR + c4 * 8) = uh;
        }
        __syncthreads();

        {
            const int gn = gt + NBLK;
            if (gn < NTILES) {
                const float4* src = (const float4*)(neigh + (size_t)gn * (ROWS_T * FF));
#pragma unroll
                for (int u = 0; u < 16; ++u) {
                    int idx = tid + u * 256;
                    if (idx < NSTG4) cp_async16(sb + SM_STG + idx * 16, src + idx);
                }
            }
            CP_COMMIT();
        }

        float acc[2][16][4];
#pragma unroll
        for (int mt = 0; mt < 2; ++mt)
#pragma unroll
            for (int nt = 0; nt < 16; ++nt)
#pragma unroll
                for (int i = 0; i < 4; ++i) acc[mt][nt][i] = 0.f;

#pragma unroll
        for (int s = 0; s < 8; ++s) {
            u32 ah[2][4];
#pragma unroll
            for (int mt = 0; mt < 2; ++mt) {
                u32 off = (u32)((m0 + mt * 16 + a_row_l) * ASTR + (s * 16 + a_koff) * 2);
                ldsm4(sb + SM_AHI + off, ah[mt][0], ah[mt][1], ah[mt][2], ah[mt][3]);
            }
#pragma unroll
            for (int nt2 = 0; nt2 < 8; ++nt2) {
                u32 bh[4];
                u32 boff = (u32)((s * 16 + a_row_l) * BSTR + (n0 + nt2 * 16 + a_koff) * 2);
                ldsm4t(sb + SM_B + boff, bh[0], bh[1], bh[2], bh[3]);
#pragma unroll
                for (int mt = 0; mt < 2; ++mt) {
                    mma16816h(acc[mt][nt2 * 2],     ah[mt], bh[0], bh[1]);
                    mma16816h(acc[mt][nt2 * 2 + 1], ah[mt], bh[2], bh[3]);
                }
            }
        }
        __syncthreads();

#pragma unroll
        for (int mt = 0; mt < 2; ++mt)
#pragma unroll
            for (int nt = 0; nt < 16; ++nt) {
                const int row = m0 + mt * 16 + g8;
                const int col = n0 + nt * 8 + tig * 2;
                u32 p0, p1;
                asm("cvt.rn.f16x2.f32 %0, %1, %2;" : "=r"(p0)
                    : "f"(acc[mt][nt][1]), "f"(acc[mt][nt][0]));
                asm("cvt.rn.f16x2.f32 %0, %1, %2;" : "=r"(p1)
                    : "f"(acc[mt][nt][3]), "f"(acc[mt][nt][2]));
                *(u32*)(smem + row * 528 + col * 2) = p0;
                *(u32*)(smem + (row + 8) * 528 + col * 2) = p1;
            }
        __syncthreads();

        {
            const float g1v = __ldg(&g1[tid]);
            const __half* zc = (const __half*)smem + tid;
#pragma unroll
            for (int grp = 0; grp < 5; ++grp) {
                const __half* zb = zc + grp * 25 * ZHSTR;
                float mx = -3.4e38f, mn = 3.4e38f;
#pragma unroll
                for (int r = 0; r < 25; ++r) {
                    float v = __half2float(zb[r * ZHSTR]);
                    mx = fmaxf(mx, v);
                    mn = fminf(mn, v);
                    sAcc += v;
                    qAcc = fmaf(v, v, qAcc);
                }
                d_poolZ[(size_t)(5 * gt + grp) * TT + tid] = (g1v >= 0.f) ? mx : mn;
            }
        }
        __syncthreads();
    }

    d_pBs2[blockIdx.x * 256 + tid] = sAcc;
    d_pBq2[blockIdx.x * 256 + tid] = qAcc;
}

// ---------------- stats1 ----------------
__global__ void __launch_bounds__(128, 1)
stats1(const float* __restrict__ g1, const float* __restrict__ b1) {
    __shared__ double ss[128], qq[128];
    const int c = blockIdx.x;
    const int t = threadIdx.x;
    double s = 0.0, q = 0.0;
    for (int i = t; i < NBLK; i += 128) {
        s += (double)d_pBs2[i * 256 + c];
        q += (double)d_pBq2[i * 256 + c];
    }
    ss[t] = s; qq[t] = q;
    __syncthreads();
#pragma unroll
    for (int w = 64; w >= 1; w >>= 1) {
        if (t < w) { ss[t] += ss[t + w]; qq[t] += qq[t + w]; }
        __syncthreads();
    }
    if (t == 0) {
        const double inv = 1.0 / (double)NKTOT;
        const double m = ss[0] * inv;
        const double var = qq[0] * inv - m * m;
        const float a = g1[c] * rsqrtf((float)var + EPSB);
        d_a1[c] = a;
        d_c1[c] = b1[c] - a * (float)m;
    }
}

// ---------------- muWnK ----------------
__global__ void __launch_bounds__(256, 1)
muWnK(const float* __restrict__ Wn, const float* __restrict__ g1,
      const float* __restrict__ b1) {
    __shared__ float red[256];
    const int j = blockIdx.x;
    const int t = threadIdx.x;
    const float mu = 1.966f * fabsf(g1[t]) + b1[t];
    red[t] = mu * Wn[t * OUTD + j];
    __syncthreads();
#pragma unroll
    for (int w = 128; w >= 1; w >>= 1) {
        if (t < w) red[t] += red[t + w];
        __syncthreads();
    }
    if (t == 0) d_muWn[j] = red[0];
}

// ================= pass C1h: SW = self @ Ws via HMMA fp16 =================
__global__ void __launch_bounds__(256, 1)
passC1h(const float* __restrict__ selfn, const float* __restrict__ Ws) {
    extern __shared__ char smem[];
    const u32 sb = smem_u32(smem);
    float* zbuf = (float*)(smem + H1Z);
    const int tid = threadIdx.x;
    const int lane = tid & 31;
    const int wid = tid >> 5;
    const int g8 = lane >> 2;
    const int tig = lane & 3;
    const int m0 = (wid & 3) * 32;
    const int n0 = (wid >> 2) * 64;
    const int a_row_l = lane & 15;
    const int a_koff = (lane >> 4) << 3;
    const int jj = tid & 127;
    const int hh = tid >> 7;

    // B = fp16(Ws): 128 k-rows x 128 cols
    for (int idx = tid; idx < 4096; idx += 256) {
        int k = idx >> 5, j4 = idx & 31;
        float4 v = ((const float4*)Ws)[idx];
        uint2 uh;
        asm("cvt.rn.f16x2.f32 %0, %1, %2;" : "=r"(uh.x) : "f"(v.y), "f"(v.x));
        asm("cvt.rn.f16x2.f32 %0, %1, %2;" : "=r"(uh.y) : "f"(v.w), "f"(v.z));
        *(uint2*)(smem + H1B + k * 272 + j4 * 8) = uh;
    }
    __syncthreads();

    float sAcc = 0.f, qAcc = 0.f;

    for (int tile = blockIdx.x; tile < NTL2; tile += C1NB) {
        // ---- convert self rows -> fp16 A ----
        for (int idx = tid; idx < 4096; idx += 256) {
            int r = idx >> 5, c4 = idx & 31;
            int node = tile * 128 + r;
            float4 v = (node < NN) ? ((const float4*)(selfn + (size_t)node * FF))[c4]
                                   : make_float4(0.f, 0.f, 0.f, 0.f);
            uint2 uh;
            asm("cvt.rn.f16x2.f32 %0, %1, %2;" : "=r"(uh.x) : "f"(v.y), "f"(v.x));
            asm("cvt.rn.f16x2.f32 %0, %1, %2;" : "=r"(uh.y) : "f"(v.w), "f"(v.z));
            *(uint2*)(smem + H1A + r * 272 + c4 * 8) = uh;
        }
        __syncthreads();

        // ---- MMA: 128x128 tile, K=128 ----
        float acc[2][8][4];
#pragma unroll
        for (int mt = 0; mt < 2; ++mt)
#pragma unroll
            for (int nt = 0; nt < 8; ++nt)
#pragma unroll
                for (int i = 0; i < 4; ++i) acc[mt][nt][i] = 0.f;

#pragma unroll
        for (int s = 0; s < 8; ++s) {
            u32 ah[2][4];
#pragma unroll
            for (int mt = 0; mt < 2; ++mt) {
                u32 off = (u32)((m0 + mt * 16 + a_row_l) * 272 + (s * 16 + a_koff) * 2);
                ldsm4(sb + H1A + off, ah[mt][0], ah[mt][1], ah[mt][2], ah[mt][3]);
            }
#pragma unroll
            for (int nt2 = 0; nt2 < 4; ++nt2) {
                u32 bh[4];
                u32 boff = (u32)((s * 16 + a_row_l) * 272 + (n0 + nt2 * 16 + a_koff) * 2);
                ldsm4t(sb + H1B + boff, bh[0], bh[1], bh[2], bh[3]);
#pragma unroll
                for (int mt = 0; mt < 2; ++mt) {
                    mma16816h(acc[mt][nt2 * 2],     ah[mt], bh[0], bh[1]);
                    mma16816h(acc[mt][nt2 * 2 + 1], ah[mt], bh[2], bh[3]);
                }
            }
        }

        // ---- fragments -> zbuf f32 (separate region; no alias hazard) ----
#pragma unroll
        for (int mt = 0; mt < 2; ++mt)
#pragma unroll
            for (int nt = 0; nt < 8; ++nt) {
                const int row = m0 + mt * 16 + g8;
                const int col = n0 + nt * 8 + tig * 2;
                float2 lo2; lo2.x = acc[mt][nt][0]; lo2.y = acc[mt][nt][1];
                float2 hi2; hi2.x = acc[mt][nt][2]; hi2.y = acc[mt][nt][3];
                *(float2*)(zbuf + row * ZST2 + col) = lo2;
                *(float2*)(zbuf + (row + 8) * ZST2 + col) = hi2;
            }
        __syncthreads();

        // ---- column sums + coalesced SW writes ----
        {
            const int rbase = tile * 128 + hh * 64;
#pragma unroll
            for (int rr = 0; rr < 64; ++rr) {
                if (rbase + rr < NN) {
                    float v = zbuf[(hh * 64 + rr) * ZST2 + jj];
                    sAcc += v;
                    qAcc = fmaf(v, v, qAcc);
                }
            }
        }
        for (int idx = tid; idx < 4096; idx += 256) {
            int r = idx >> 5, c4 = idx & 31;
            int grow = tile * 128 + r;
            if (grow < NN)
                ((float4*)(d_SW + (size_t)grow * OUTD))[c4] =
                    *(const float4*)(zbuf + r * ZST2 + c4 * 4);
        }
        __syncthreads();   // zbuf reads done before next tile's writes
    }

    d_pC1s[blockIdx.x * 256 + tid] = sAcc;
    d_pC1q[blockIdx.x * 256 + tid] = qAcc;
}

// ================= pass C2h: byte-identical to R16 =================
__global__ void __launch_bounds__(256, 1)
passC2h(const float* __restrict__ Wn, const float* __restrict__ g1,
        const float* __restrict__ b1) {
    extern __shared__ char smem[];
    const u32 sb = smem_u32(smem);
    float* a1s  = (float*)(smem + C2AC);
    float* c1s  = a1s + 256;
    float* muWn = c1s + 256;
    float* zbuf = (float*)smem;
    const int tid = threadIdx.x;
    const int lane = tid & 31;
    const int wid = tid >> 5;
    const int g8 = lane >> 2;
    const int tig = lane & 3;
    const int m0 = (wid & 3) * 32;
    const int n0 = (wid >> 2) * 64;
    const int a_row_l = lane & 15;
    const int a_koff = (lane >> 4) << 3;
    const int jj = tid & 127;
    const int hh = tid >> 7;

    a1s[tid] = d_a1[tid];
    c1s[tid] = d_c1[tid] - (1.966f * fabsf(g1[tid]) + b1[tid]);
    if (tid < 128) muWn[tid] = d_muWn[tid];

    for (int idx = tid; idx < 8192; idx += 256) {
        int k = idx >> 5, j4 = idx & 31;
        float4 v = ((const float4*)Wn)[idx];
        uint2 uh;
        asm("cvt.rn.f16x2.f32 %0, %1, %2;" : "=r"(uh.x) : "f"(v.y), "f"(v.x));
        asm("cvt.rn.f16x2.f32 %0, %1, %2;" : "=r"(uh.y) : "f"(v.w), "f"(v.z));
        *(uint2*)(smem + C2B + k * 272 + j4 * 8) = uh;
    }
    __syncthreads();

    float sAcc = 0.f, qAcc = 0.f;

    for (int tile = blockIdx.x; tile < NTL2; tile += C2NB) {
        __syncthreads();

        for (int idx = tid; idx < 8192; idx += 256) {
            int r = idx >> 6, t4 = idx & 63;
            int node = tile * 128 + r;
            float4 x;
            if (node < NN) {
                float4 v = ((const float4*)(d_poolZ + (size_t)node * TT))[t4];
                float4 a = ((const float4*)a1s)[t4];
                float4 c = ((const float4*)c1s)[t4];
                x.x = fmaf(a.x, v.x, c.x);
                x.y = fmaf(a.y, v.y, c.y);
                x.z = fmaf(a.z, v.z, c.z);
                x.w = fmaf(a.w, v.w, c.w);
            } else {
                x = make_float4(0.f, 0.f, 0.f, 0.f);
            }
            uint2 uh;
            asm("cvt.rn.f16x2.f32 %0, %1, %2;" : "=r"(uh.x) : "f"(x.y), "f"(x.x));
            asm("cvt.rn.f16x2.f32 %0, %1, %2;" : "=r"(uh.y) : "f"(x.w), "f"(x.z));
            *(uint2*)(smem + C2A + r * 528 + t4 * 8) = uh;
        }
        __syncthreads();

        float acc[2][8][4];
#pragma unroll
        for (int mt = 0; mt < 2; ++mt)
#pragma unroll
            for (int nt = 0; nt < 8; ++nt)
#pragma unroll
                for (int i = 0; i < 4; ++i) acc[mt][nt][i] = 0.f;

#pragma unroll
        for (int s = 0; s < 16; ++s) {
            u32 ah[2][4];
#pragma unroll
            for (int mt = 0; mt < 2; ++mt) {
                u32 off = (u32)((m0 + mt * 16 + a_row_l) * 528 + (s * 16 + a_koff) * 2);
                ldsm4(sb + C2A + off, ah[mt][0], ah[mt][1], ah[mt][2], ah[mt][3]);
            }
#pragma unroll
            for (int nt2 = 0; nt2 < 4; ++nt2) {
                u32 bh[4];
                u32 boff = (u32)((s * 16 + a_row_l) * 272 + (n0 + nt2 * 16 + a_koff) * 2);
                ldsm4t(sb + C2B + boff, bh[0], bh[1], bh[2], bh[3]);
#pragma unroll
                for (int mt = 0; mt < 2; ++mt) {
                    mma16816h(acc[mt][nt2 * 2],     ah[mt], bh[0], bh[1]);
                    mma16816h(acc[mt][nt2 * 2 + 1], ah[mt], bh[2], bh[3]);
                }
            }
        }
        __syncthreads();

#pragma unroll
        for (int mt = 0; mt < 2; ++mt)
#pragma unroll
            for (int nt = 0; nt < 8; ++nt) {
                const int row = m0 + mt * 16 + g8;
                const int col = n0 + nt * 8 + tig * 2;
                float2 lo2; lo2.x = acc[mt][nt][0]; lo2.y = acc[mt][nt][1];
                float2 hi2; hi2.x = acc[mt][nt][2]; hi2.y = acc[mt][nt][3];
                *(float2*)(zbuf + row * ZST2 + col) = lo2;
                *(float2*)(zbuf + (row + 8) * ZST2 + col) = hi2;
            }
        __syncthreads();

        {
            const float mw = muWn[jj];
            const int rbase = tile * 128 + hh * 64;
#pragma unroll
            for (int rr = 0; rr < 64; ++rr) {
                if (rbase + rr < NN) {
                    float v = zbuf[(hh * 64 + rr) * ZST2 + jj] + mw;
                    sAcc += v;
                    qAcc = fmaf(v, v, qAcc);
                }
            }
        }
        for (int idx = tid; idx < 4096; idx += 256) {
            int r = idx >> 5, c4 = idx & 31;
            int grow = tile * 128 + r;
            if (grow < NN) {
                float4 v = *(const float4*)(zbuf + r * ZST2 + c4 * 4);
                float4 mw4 = ((const float4*)muWn)[c4];
                v.x += mw4.x; v.y += mw4.y; v.z += mw4.z; v.w += mw4.w;
                ((float4*)(d_PW + (size_t)grow * OUTD))[c4] = v;
            }
        }
    }

    d_pC2s[blockIdx.x * 256 + tid] = sAcc;
    d_pC2q[blockIdx.x * 256 + tid] = qAcc;
}

// ---------------- stats2 ----------------
__global__ void __launch_bounds__(128, 1)
stats2(const float* __restrict__ g2, const float* __restrict__ b2) {
    __shared__ double ss[128], qq[128];
    const int c = blockIdx.x;
    const int t = threadIdx.x;
    double s = 0.0, q = 0.0;
    if (c < 128) {
        for (int i = t; i < C1NB * 2; i += 128) {
            const int b = i >> 1, off = (i & 1) * 128;
            s += (double)d_pC1s[b * 256 + off + c];
            q += (double)d_pC1q[b * 256 + off + c];
        }
    } else {
        const int jr = c - 128;
        for (int i = t; i < C2NB * 2; i += 128) {
            const int b = i >> 1, off = (i & 1) * 128;
            s += (double)d_pC2s[b * 256 + off + jr];
            q += (double)d_pC2q[b * 256 + off + jr];
        }
    }
    ss[t] = s; qq[t] = q;
    __syncthreads();
#pragma unroll
    for (int w = 64; w >= 1; w >>= 1) {
        if (t < w) { ss[t] += ss[t + w]; qq[t] += qq[t + w]; }
        __syncthreads();
    }
    if (t == 0) {
        const double inv = 1.0 / (double)NN;
        const double m = ss[0] * inv;
        const double var = qq[0] * inv - m * m;
        const float a = g2[c] * rsqrtf((float)var + EPSB);
        d_a2[c] = a;
        d_c2[c] = b2[c] - a * (float)m;
    }
}

// ---------------- pass E ----------------
__global__ void passE(float* __restrict__ out) {
    const int base = (blockIdx.x * blockDim.x + threadIdx.x) * 4;
#pragma unroll
    for (int u = 0; u < 4; ++u) {
        const int idx = base + u;
        if (idx >= NN * 64) return;
        const int n = idx >> 6;
        const int c4 = idx & 63;
        float4 v;
        if (c4 < 32) v = ((const float4*)d_SW)[(size_t)n * 32 + c4];
        else         v = ((const float4*)d_PW)[(size_t)n * 32 + (c4 - 32)];
        const float4 a = ((const float4*)d_a2)[c4];
        const float4 c = ((const float4*)d_c2)[c4];
        float4 r;
        r.x = fmaxf(0.f, fmaf(a.x, v.x, c.x));
        r.y = fmaxf(0.f, fmaf(a.y, v.y, c.y));
        r.z = fmaxf(0.f, fmaf(a.z, v.z, c.z));
        r.w = fmaxf(0.f, fmaf(a.w, v.w, c.w));
        ((float4*)out)[idx] = r;
    }
}

// ---------------- launch ----------------
extern "C" void kernel_launch(void* const* d_in, const int* in_sizes, int n_in,
                              void* d_out, int out_size) {
    const float* selfn = (const float*)d_in[0];
    const float* neigh = (const float*)d_in[1];
    const float* Wt = (const float*)d_in[3];
    const float* g1 = (const float*)d_in[5];
    const float* b1 = (const float*)d_in[6];
    const float* Wn = (const float*)d_in[7];
    const float* Ws = (const float*)d_in[8];
    const float* g2 = (const float*)d_in[9];
    const float* b2 = (const float*)d_in[10];
    float* out = (float*)d_out;

    static int configured = 0;
    if (!configured) {
        cudaFuncSetAttribute(passB, cudaFuncAttributeMaxDynamicSharedMemorySize, SM_TOTAL);
        cudaFuncSetAttribute(passC1h, cudaFuncAttributeMaxDynamicSharedMemorySize, SM1_TOTAL);
        cudaFuncSetAttribute(passC2h, cudaFuncAttributeMaxDynamicSharedMemorySize, SM2_TOTAL);
        configured = 1;
    }

    passB<<<NBLK, 256, SM_TOTAL>>>(neigh, Wt, g1);
    stats1<<<256, 128>>>(g1, b1);
    muWnK<<<128, 256>>>(Wn, g1, b1);
    passC1h<<<C1NB, 256, SM1_TOTAL>>>(selfn, Ws);
    passC2h<<<C2NB, 256, SM2_TOTAL>>>(Wn, g1, b1);
    stats2<<<256, 128>>>(g2, b2);
    passE<<<(NN * 64 + 1023) / 1024, 256>>>(out);
}